// round 15
// baseline (speedup 1.0000x reference)
#include <cuda_runtime.h>

#define B_ 64
#define J_ 25
#define V_ 50000
#define VT 128          // threads per block
#define VPT 2           // vertices per thread
#define VT2 (VT*VPT)    // 256 vertices per block
#define NB 8            // batches per skin tile
#define NPAIR (NB/2)
#define WSTR 258        // transposed-weight row stride
#define GRIDX ((V_ + VT2 - 1) / VT2)   // 196
#define GRIDY (B_ / NB)                // 8
#define NBLOCKS (GRIDX * GRIDY)        // 1568

// Device globals (no allocation allowed); zero-initialized.
__device__ float g_T[B_*J_*12];   // per-(b,j) skinning transform (3x4 row-major)
__device__ int   g_flag;          // fk-done counter (0 -> 2 -> reset 0)
__device__ int   g_done;          // gate-passed counter (reset 0)

// ---------------------------------------------------------------------------
// f32x2 packed helpers (sm_100+)
// ---------------------------------------------------------------------------
__device__ __forceinline__ unsigned long long pack2(float lo, float hi) {
    unsigned long long d;
    asm("mov.b64 %0, {%1, %2};" : "=l"(d)
        : "r"(__float_as_uint(lo)), "r"(__float_as_uint(hi)));
    return d;
}
__device__ __forceinline__ unsigned long long pack2s(float w) {
    unsigned long long d;
    asm("mov.b64 %0, {%1, %1};" : "=l"(d) : "r"(__float_as_uint(w)));
    return d;
}
__device__ __forceinline__ void unpack2(unsigned long long s, float& lo, float& hi) {
    unsigned int a, b;
    asm("mov.b64 {%0, %1}, %2;" : "=r"(a), "=r"(b) : "l"(s));
    lo = __uint_as_float(a); hi = __uint_as_float(b);
}
__device__ __forceinline__ void fma2acc(unsigned long long& d,
                                        unsigned long long a,
                                        unsigned long long b) {
    asm("fma.rn.f32x2 %0, %1, %2, %0;" : "+l"(d) : "l"(a), "l"(b));
}
__device__ __forceinline__ unsigned long long fma2(unsigned long long a,
                                                   unsigned long long b,
                                                   unsigned long long c) {
    unsigned long long d;
    asm("fma.rn.f32x2 %0, %1, %2, %3;" : "=l"(d) : "l"(a), "l"(b), "l"(c));
    return d;
}

// ---------------------------------------------------------------------------
// Fused FK + skinning kernel (single launch).
// Blocks (0,0)/(0,1) compute FK for batches 0-31 / 32-63 into g_T (smem union
// with the skin stage buffers), then signal g_flag. ALL blocks stage their
// weight tile BEFORE gating on g_flag==2, hiding fk latency. Last block
// through the gate resets flags (replay-deterministic). Skin body = R13.
// ---------------------------------------------------------------------------
struct __align__(16) FusedSmem {
    // fk view:   ls[32*25*12] (38400B) + gpis[400] (1600B) + par[25] (100B)
    //            = 40100 B
    // skin view: ws_t[25*258] (25800B) + pad-to-16 + Ts[4*25*12]xfloat2
    //            (9600B) = 35408 B
    unsigned char raw[40112];     // max(40100, 35408) rounded to 16
};

__global__ __launch_bounds__(VT, 5)
void fused_kernel(const float* __restrict__ je,
                  const float* __restrict__ lp,
                  const float* __restrict__ sc,
                  const float* __restrict__ gpi,
                  const int* __restrict__ parents,
                  const float* __restrict__ vtx,
                  const float* __restrict__ W,
                  const float* __restrict__ pc,
                  const float* __restrict__ ic,
                  float* __restrict__ out) {
    __shared__ FusedSmem sm;

    float* joint_out = out;
    float* mesh_out  = out + B_*J_*3;

    int tid = threadIdx.x;
    int fkrole = (blockIdx.x == 0 && blockIdx.y < 2) ? (int)blockIdx.y : -1;

    // =======================  FK (2 blocks only)  =======================
    if (fkrole >= 0) {
        float* ls   = reinterpret_cast<float*>(sm.raw);            // 9600 f
        float* gpis = ls + 32*J_*12;                               // 400 f
        int*   par  = reinterpret_cast<int*>(gpis + 400);          // 25 i
        int bbase = fkrole * 32;

        for (int i = tid; i < J_*16; i += VT) gpis[i] = gpi[i];
        if (tid < J_) par[tid] = parents[tid];
        __syncthreads();

        // locals = (local_pose with t += skel_corr) @ euler2mat(joint_euler)
        for (int idx = tid; idx < 32 * J_; idx += VT) {
            int j = idx % J_;
            int gidx = bbase * J_ + idx;
            float ex = je[gidx*3+0], ey = je[gidx*3+1], ez = je[gidx*3+2];
            float sx, cx, sy, cy, sz, cz;
            sincosf(ex, &sx, &cx);
            sincosf(ey, &sy, &cy);
            sincosf(ez, &sz, &cz);
            float R00 = cz*cy, R01 = cz*sy*sx - sz*cx, R02 = cz*sy*cx + sz*sx;
            float R10 = sz*cy, R11 = sz*sy*sx + cz*cx, R12 = sz*sy*cx - cz*sx;
            float R20 = -sy,   R21 = cy*sx,            R22 = cy*cx;
            const float* L0 = lp + j*16;
            float* o = ls + idx*12;
            #pragma unroll
            for (int r = 0; r < 3; ++r) {
                float a0 = L0[r*4+0], a1 = L0[r*4+1], a2 = L0[r*4+2];
                o[r*4+0] = a0*R00 + a1*R10 + a2*R20;
                o[r*4+1] = a0*R01 + a1*R11 + a2*R21;
                o[r*4+2] = a0*R02 + a1*R12 + a2*R22;
                o[r*4+3] = L0[r*4+3] + sc[j*3+r];
            }
        }
        __syncthreads();

        // sequential chain, thread = (batch-local, row)
        if (tid < 32 * 3) {
            int bl = tid / 3, r = tid % 3;
            int b = bbase + bl;
            float Grow[J_][4];
            float pr0 = 0.f, pr1 = 0.f, pr2 = 0.f, pr3 = 0.f;
            int prevj = -2;
            for (int j = 0; j < J_; ++j) {
                int pj = par[j];
                float g0, g1, g2, g3;
                if (pj < 0) {
                    g0 = (r == 0) ? 1.f : 0.f;
                    g1 = (r == 1) ? 1.f : 0.f;
                    g2 = (r == 2) ? 1.f : 0.f;
                    g3 = 0.f;
                } else {
                    float p0, p1, p2, p3;
                    if (pj == prevj) { p0 = pr0; p1 = pr1; p2 = pr2; p3 = pr3; }
                    else { p0 = Grow[pj][0]; p1 = Grow[pj][1];
                           p2 = Grow[pj][2]; p3 = Grow[pj][3]; }
                    const float* L = ls + (bl*J_ + j) * 12;
                    g0 = p0*L[0] + p1*L[4] + p2*L[8];
                    g1 = p0*L[1] + p1*L[5] + p2*L[9];
                    g2 = p0*L[2] + p1*L[6] + p2*L[10];
                    g3 = p0*L[3] + p1*L[7] + p2*L[11] + p3;
                }
                Grow[j][0] = g0; Grow[j][1] = g1;
                Grow[j][2] = g2; Grow[j][3] = g3;
                pr0 = g0; pr1 = g1; pr2 = g2; pr3 = g3; prevj = j;

                const float* P = gpis + j*16;
                float4 t4;
                t4.x = g0*P[0] + g1*P[4] + g2*P[8];
                t4.y = g0*P[1] + g1*P[5] + g2*P[9];
                t4.z = g0*P[2] + g1*P[6] + g2*P[10];
                t4.w = g0*P[3] + g1*P[7] + g2*P[11] + g3;
                *reinterpret_cast<float4*>(g_T + (b*J_ + j)*12 + r*4) = t4;
                joint_out[(b*J_ + j)*3 + r] = g3;
            }
        }
        __threadfence();
        __syncthreads();                 // smem (ls) dead after this point
        if (tid == 0) atomicAdd(&g_flag, 1);
    }

    // =======================  Skin (all blocks)  =======================
    float* ws_t = reinterpret_cast<float*>(sm.raw);                // 6450 f
    float2* Ts  = reinterpret_cast<float2*>(sm.raw + ((J_*WSTR*4 + 15) & ~15));

    int v0 = blockIdx.x * VT2;
    int b0base = blockIdx.y * NB;
    int nv = min(VT2, V_ - v0);   // V_%2==0 -> nv%2==0

    // Stage weights (independent of g_T -> overlaps fk latency)
    for (int i = tid; i < nv * J_; i += VT) {
        int vv = i / J_;
        int j  = i - vv * J_;
        ws_t[j * WSTR + vv] = W[(size_t)v0 * J_ + i];
    }

    // Gate: wait until both fk halves are published
    if (tid == 0) {
        while (*(volatile int*)&g_flag < 2) __nanosleep(128);
    }
    __syncthreads();

    // Stage T for NB batches, interleaved per batch pair
    for (int i = tid; i < NPAIR * J_ * 12; i += VT) {
        int p = i / (J_ * 12);
        int rem = i - p * (J_ * 12);
        int b0 = b0base + 2 * p;
        Ts[i] = make_float2(g_T[b0 * (J_*12) + rem],
                            g_T[(b0 + 1) * (J_*12) + rem]);
    }
    __syncthreads();

    // Flag reset by the LAST block through the gate (all 1568 counted)
    if (tid == 0) {
        int d = atomicAdd(&g_done, 1);
        if (d == NBLOCKS - 1) {
            atomicExch(&g_done, 0);
            atomicExch(&g_flag, 0);
        }
    }

    int lv = VPT * tid;
    if (lv >= nv) return;          // no further barriers below
    int vA = v0 + lv;
    int vB = vA + 1;

    float vAx = vtx[vA*3+0], vAy = vtx[vA*3+1], vAz = vtx[vA*3+2];
    float vBx = vtx[vB*3+0], vBy = vtx[vB*3+1], vBz = vtx[vB*3+2];

    const int strideB = V_ * 3;
    const int base = b0base * strideB + vA * 3;

    const float* wb = ws_t + lv;

    #pragma unroll 1
    for (int p = 0; p < NPAIR; ++p) {
        int o0 = base + (2 * p) * strideB;
        int o1 = o0 + strideB;

        unsigned long long MA[12], MB[12];
        #pragma unroll
        for (int k = 0; k < 12; ++k) { MA[k] = 0ull; MB[k] = 0ull; }

        const ulonglong2* tb =
            reinterpret_cast<const ulonglong2*>(Ts + p * (J_ * 12));
        #pragma unroll 5
        for (int j = 0; j < J_; ++j) {
            float2 wv = *reinterpret_cast<const float2*>(wb + j * WSTR);
            unsigned long long wA = pack2s(wv.x);
            unsigned long long wB = pack2s(wv.y);
            const ulonglong2* trow = tb + j * 6;
            #pragma unroll
            for (int m = 0; m < 6; ++m) {
                ulonglong2 q = trow[m];
                fma2acc(MA[2*m],   q.x, wA); fma2acc(MA[2*m+1], q.y, wA);
                fma2acc(MB[2*m],   q.x, wB); fma2acc(MB[2*m+1], q.y, wB);
            }
        }

        float2 pA0 = *(const float2*)(pc + o0);
        float2 pA1 = *(const float2*)(pc + o0 + 2);
        float2 pA2 = *(const float2*)(pc + o0 + 4);
        float2 pB0 = *(const float2*)(pc + o1);
        float2 pB1 = *(const float2*)(pc + o1 + 2);
        float2 pB2 = *(const float2*)(pc + o1 + 4);
        float2 iA0 = *(const float2*)(ic + o0);
        float2 iA1 = *(const float2*)(ic + o0 + 2);
        float2 iA2 = *(const float2*)(ic + o0 + 4);
        float2 iB0 = *(const float2*)(ic + o1);
        float2 iB1 = *(const float2*)(ic + o1 + 2);
        float2 iB2 = *(const float2*)(ic + o1 + 4);

        unsigned long long ppxA = pack2(vAx + pA0.x + iA0.x, vAx + pB0.x + iB0.x);
        unsigned long long ppyA = pack2(vAy + pA0.y + iA0.y, vAy + pB0.y + iB0.y);
        unsigned long long ppzA = pack2(vAz + pA1.x + iA1.x, vAz + pB1.x + iB1.x);
        unsigned long long ppxB = pack2(vBx + pA1.y + iA1.y, vBx + pB1.y + iB1.y);
        unsigned long long ppyB = pack2(vBy + pA2.x + iA2.x, vBy + pB2.x + iB2.x);
        unsigned long long ppzB = pack2(vBz + pA2.y + iA2.y, vBz + pB2.y + iB2.y);

        float a0x, a1x, a0y, a1y, a0z, a1z;
        float b0x, b1x, b0y, b1y, b0z, b1z;
        {
            unsigned long long o;
            o = fma2(MA[2], ppzA, MA[3]); o = fma2(MA[1], ppyA, o); o = fma2(MA[0], ppxA, o);
            unpack2(o, a0x, a1x);
            o = fma2(MA[6], ppzA, MA[7]); o = fma2(MA[5], ppyA, o); o = fma2(MA[4], ppxA, o);
            unpack2(o, a0y, a1y);
            o = fma2(MA[10], ppzA, MA[11]); o = fma2(MA[9], ppyA, o); o = fma2(MA[8], ppxA, o);
            unpack2(o, a0z, a1z);
            o = fma2(MB[2], ppzB, MB[3]); o = fma2(MB[1], ppyB, o); o = fma2(MB[0], ppxB, o);
            unpack2(o, b0x, b1x);
            o = fma2(MB[6], ppzB, MB[7]); o = fma2(MB[5], ppyB, o); o = fma2(MB[4], ppxB, o);
            unpack2(o, b0y, b1y);
            o = fma2(MB[10], ppzB, MB[11]); o = fma2(MB[9], ppyB, o); o = fma2(MB[8], ppxB, o);
            unpack2(o, b0z, b1z);
        }

        *(float2*)(mesh_out + o0)     = make_float2(a0x, a0y);
        *(float2*)(mesh_out + o0 + 2) = make_float2(a0z, b0x);
        *(float2*)(mesh_out + o0 + 4) = make_float2(b0y, b0z);
        *(float2*)(mesh_out + o1)     = make_float2(a1x, a1y);
        *(float2*)(mesh_out + o1 + 2) = make_float2(a1z, b1x);
        *(float2*)(mesh_out + o1 + 4) = make_float2(b1y, b1z);
    }
}

// ---------------------------------------------------------------------------
extern "C" void kernel_launch(void* const* d_in, const int* in_sizes, int n_in,
                              void* d_out, int out_size) {
    const float* joint_euler = (const float*)d_in[0];
    const float* vtx         = (const float*)d_in[1];
    const float* W           = (const float*)d_in[2];
    const float* local_pose  = (const float*)d_in[3];
    const float* gpi         = (const float*)d_in[4];
    const float* sc          = (const float*)d_in[5];
    const float* pc          = (const float*)d_in[6];
    const float* ic          = (const float*)d_in[7];
    const int*   parents     = (const int*)d_in[8];
    float* out = (float*)d_out;

    dim3 grid(GRIDX, GRIDY);
    fused_kernel<<<grid, VT>>>(joint_euler, local_pose, sc, gpi, parents,
                               vtx, W, pc, ic, out);
}

// round 16
// speedup vs baseline: 1.0625x; 1.0625x over previous
#include <cuda_runtime.h>

#define B_ 64
#define J_ 25
#define V_ 50000
#define VT 128          // threads per skin block
#define VPT 2           // vertices per thread (consecutive; V_%2==0)
#define VT2 (VT*VPT)    // 256 vertices per block
#define NB 8            // batches per skin block
#define NPAIR (NB/2)
#define WSTR 258        // transposed-weight row stride (even -> 8B-aligned rows)

// Scratch (device global; no allocation allowed)
__device__ float g_T[B_*J_*12];   // per-(b,j) skinning transform (3x4 row-major)

// ---------------------------------------------------------------------------
// FK kernel: one block per batch (64 blocks x 128 threads). Thread j (<25)
// computes joint j's local matrix into smem; threads r (<3) then run the
// 25-step sequential chain from smem. Spreads fk over 64 SMs with a short
// per-block critical path.
// ---------------------------------------------------------------------------
__global__ __launch_bounds__(128)
void fk_kernel(const float* __restrict__ je,
               const float* __restrict__ lp,
               const float* __restrict__ sc,
               const float* __restrict__ gpi,
               const int* __restrict__ parents,
               float* __restrict__ joint_out) {
    __shared__ float ls[J_ * 12];
    __shared__ float gpis[J_ * 16];
    __shared__ int   par[J_];

    int tid = threadIdx.x;
    int b = blockIdx.x;

    for (int i = tid; i < J_ * 16; i += 128) gpis[i] = gpi[i];
    if (tid < J_) par[tid] = parents[tid];

    if (tid < J_) {
        int j = tid;
        int gidx = b * J_ + j;
        float ex = je[gidx*3+0], ey = je[gidx*3+1], ez = je[gidx*3+2];
        float sx, cx, sy, cy, sz, cz;
        sincosf(ex, &sx, &cx);
        sincosf(ey, &sy, &cy);
        sincosf(ez, &sz, &cz);
        float R00 = cz*cy, R01 = cz*sy*sx - sz*cx, R02 = cz*sy*cx + sz*sx;
        float R10 = sz*cy, R11 = sz*sy*sx + cz*cx, R12 = sz*sy*cx - cz*sx;
        float R20 = -sy,   R21 = cy*sx,            R22 = cy*cx;
        const float* L0 = lp + j*16;
        float* o = ls + j*12;
        #pragma unroll
        for (int r = 0; r < 3; ++r) {
            float a0 = L0[r*4+0], a1 = L0[r*4+1], a2 = L0[r*4+2];
            o[r*4+0] = a0*R00 + a1*R10 + a2*R20;
            o[r*4+1] = a0*R01 + a1*R11 + a2*R21;
            o[r*4+2] = a0*R02 + a1*R12 + a2*R22;
            o[r*4+3] = L0[r*4+3] + sc[j*3+r];
        }
    }
    __syncthreads();

    if (tid >= 3) return;
    int r = tid;

    float Grow[J_][4];
    float pr0 = 0.f, pr1 = 0.f, pr2 = 0.f, pr3 = 0.f;
    int prevj = -2;
    for (int j = 0; j < J_; ++j) {
        int pj = par[j];
        float g0, g1, g2, g3;
        if (pj < 0) {
            g0 = (r == 0) ? 1.f : 0.f;
            g1 = (r == 1) ? 1.f : 0.f;
            g2 = (r == 2) ? 1.f : 0.f;
            g3 = 0.f;
        } else {
            float p0, p1, p2, p3;
            if (pj == prevj) { p0 = pr0; p1 = pr1; p2 = pr2; p3 = pr3; }
            else { p0 = Grow[pj][0]; p1 = Grow[pj][1]; p2 = Grow[pj][2]; p3 = Grow[pj][3]; }
            const float* L = ls + j * 12;
            g0 = p0*L[0] + p1*L[4] + p2*L[8];
            g1 = p0*L[1] + p1*L[5] + p2*L[9];
            g2 = p0*L[2] + p1*L[6] + p2*L[10];
            g3 = p0*L[3] + p1*L[7] + p2*L[11] + p3;
        }
        Grow[j][0] = g0; Grow[j][1] = g1; Grow[j][2] = g2; Grow[j][3] = g3;
        pr0 = g0; pr1 = g1; pr2 = g2; pr3 = g3; prevj = j;

        const float* P = gpis + j*16;
        float4 t4;
        t4.x = g0*P[0] + g1*P[4] + g2*P[8];
        t4.y = g0*P[1] + g1*P[5] + g2*P[9];
        t4.z = g0*P[2] + g1*P[6] + g2*P[10];
        t4.w = g0*P[3] + g1*P[7] + g2*P[11] + g3;
        *reinterpret_cast<float4*>(g_T + (b*J_ + j)*12 + r*4) = t4;
        joint_out[(b*J_ + j)*3 + r] = g3;
    }
}

// ---------------------------------------------------------------------------
// f32x2 packed helpers (sm_100+)
// ---------------------------------------------------------------------------
__device__ __forceinline__ unsigned long long pack2(float lo, float hi) {
    unsigned long long d;
    asm("mov.b64 %0, {%1, %2};" : "=l"(d)
        : "r"(__float_as_uint(lo)), "r"(__float_as_uint(hi)));
    return d;
}
__device__ __forceinline__ unsigned long long pack2s(float w) {
    unsigned long long d;
    asm("mov.b64 %0, {%1, %1};" : "=l"(d) : "r"(__float_as_uint(w)));
    return d;
}
__device__ __forceinline__ void unpack2(unsigned long long s, float& lo, float& hi) {
    unsigned int a, b;
    asm("mov.b64 {%0, %1}, %2;" : "=r"(a), "=r"(b) : "l"(s));
    lo = __uint_as_float(a); hi = __uint_as_float(b);
}
__device__ __forceinline__ void fma2acc(unsigned long long& d,
                                        unsigned long long a,
                                        unsigned long long b) {
    asm("fma.rn.f32x2 %0, %1, %2, %0;" : "+l"(d) : "l"(a), "l"(b));
}
__device__ __forceinline__ unsigned long long fma2(unsigned long long a,
                                                   unsigned long long b,
                                                   unsigned long long c) {
    unsigned long long d;
    asm("fma.rn.f32x2 %0, %1, %2, %3;" : "=l"(d) : "l"(a), "l"(b), "l"(c));
    return d;
}

// ---------------------------------------------------------------------------
// Skinning kernel — R13 verbatim (measured structural optimum of the scalar
// formulation: L1 ~70% binding, fma ~50%, 96 regs, 5 blocks/SM).
// ---------------------------------------------------------------------------
__global__ __launch_bounds__(VT, 5)
void skin_kernel(const float* __restrict__ vtx,
                 const float* __restrict__ W,
                 const float* __restrict__ pc,
                 const float* __restrict__ ic,
                 float* __restrict__ mesh_out) {
    __shared__ float ws_t[J_ * WSTR];                     // 25.8 KB, transposed
    __shared__ __align__(16) float2 Ts[NPAIR * J_ * 12];  // 9.6 KB

    int tid = threadIdx.x;
    int v0 = blockIdx.x * VT2;
    int b0base = blockIdx.y * NB;
    int nv = min(VT2, V_ - v0);   // V_%2==0 -> nv%2==0

    // Stage weights transposed: ws_t[j*WSTR + vv] = W[v0+vv][j]
    for (int i = tid; i < nv * J_; i += VT) {
        int vv = i / J_;
        int j  = i - vv * J_;
        ws_t[j * WSTR + vv] = W[(size_t)v0 * J_ + i];
    }
    // Stage T for NB batches, interleaved per batch pair
    for (int i = tid; i < NPAIR * J_ * 12; i += VT) {
        int p = i / (J_ * 12);
        int rem = i - p * (J_ * 12);
        int b0 = b0base + 2 * p;
        Ts[i] = make_float2(g_T[b0 * (J_*12) + rem],
                            g_T[(b0 + 1) * (J_*12) + rem]);
    }
    __syncthreads();

    int lv = VPT * tid;            // local vertex base
    if (lv >= nv) return;          // all-or-nothing (nv%2==0)
    int vA = v0 + lv;
    int vB = vA + 1;

    float vAx = vtx[vA*3+0], vAy = vtx[vA*3+1], vAz = vtx[vA*3+2];
    float vBx = vtx[vB*3+0], vBy = vtx[vB*3+1], vBz = vtx[vB*3+2];

    const int strideB = V_ * 3;                          // 150000
    const int base = b0base * strideB + vA * 3;          // < 9.6M, fits int

    const float* wb = ws_t + lv;

    #pragma unroll 1
    for (int p = 0; p < NPAIR; ++p) {
        int o0 = base + (2 * p) * strideB;   // batch b0: [Ax Ay Az Bx By Bz]
        int o1 = o0 + strideB;               // batch b1

        // ---- blend: M = sum_j w[v][j] * T[pair j] ----
        unsigned long long MA[12], MB[12];
        #pragma unroll
        for (int k = 0; k < 12; ++k) { MA[k] = 0ull; MB[k] = 0ull; }

        const ulonglong2* tb =
            reinterpret_cast<const ulonglong2*>(Ts + p * (J_ * 12));
        #pragma unroll 5
        for (int j = 0; j < J_; ++j) {
            float2 wv = *reinterpret_cast<const float2*>(wb + j * WSTR);
            unsigned long long wA = pack2s(wv.x);
            unsigned long long wB = pack2s(wv.y);
            const ulonglong2* trow = tb + j * 6;   // 12 float2 = 6 x 16B
            #pragma unroll
            for (int m = 0; m < 6; ++m) {
                ulonglong2 q = trow[m];
                fma2acc(MA[2*m],   q.x, wA); fma2acc(MA[2*m+1], q.y, wA);
                fma2acc(MB[2*m],   q.x, wB); fma2acc(MB[2*m+1], q.y, wB);
            }
        }

        // ---- load correctives ----
        float2 pA0 = *(const float2*)(pc + o0);
        float2 pA1 = *(const float2*)(pc + o0 + 2);
        float2 pA2 = *(const float2*)(pc + o0 + 4);
        float2 pB0 = *(const float2*)(pc + o1);
        float2 pB1 = *(const float2*)(pc + o1 + 2);
        float2 pB2 = *(const float2*)(pc + o1 + 4);
        float2 iA0 = *(const float2*)(ic + o0);
        float2 iA1 = *(const float2*)(ic + o0 + 2);
        float2 iA2 = *(const float2*)(ic + o0 + 4);
        float2 iB0 = *(const float2*)(ic + o1);
        float2 iB1 = *(const float2*)(ic + o1 + 2);
        float2 iB2 = *(const float2*)(ic + o1 + 4);

        // ---- pack coords over {b0, b1} ----
        unsigned long long ppxA = pack2(vAx + pA0.x + iA0.x, vAx + pB0.x + iB0.x);
        unsigned long long ppyA = pack2(vAy + pA0.y + iA0.y, vAy + pB0.y + iB0.y);
        unsigned long long ppzA = pack2(vAz + pA1.x + iA1.x, vAz + pB1.x + iB1.x);
        unsigned long long ppxB = pack2(vBx + pA1.y + iA1.y, vBx + pB1.y + iB1.y);
        unsigned long long ppyB = pack2(vBy + pA2.x + iA2.x, vBy + pB2.x + iB2.x);
        unsigned long long ppzB = pack2(vBz + pA2.y + iA2.y, vBz + pB2.y + iB2.y);

        float a0x, a1x, a0y, a1y, a0z, a1z;   // vertex A rows {b0,b1}
        float b0x, b1x, b0y, b1y, b0z, b1z;   // vertex B rows {b0,b1}
        {
            unsigned long long o;
            o = fma2(MA[2], ppzA, MA[3]); o = fma2(MA[1], ppyA, o); o = fma2(MA[0], ppxA, o);
            unpack2(o, a0x, a1x);
            o = fma2(MA[6], ppzA, MA[7]); o = fma2(MA[5], ppyA, o); o = fma2(MA[4], ppxA, o);
            unpack2(o, a0y, a1y);
            o = fma2(MA[10], ppzA, MA[11]); o = fma2(MA[9], ppyA, o); o = fma2(MA[8], ppxA, o);
            unpack2(o, a0z, a1z);
            o = fma2(MB[2], ppzB, MB[3]); o = fma2(MB[1], ppyB, o); o = fma2(MB[0], ppxB, o);
            unpack2(o, b0x, b1x);
            o = fma2(MB[6], ppzB, MB[7]); o = fma2(MB[5], ppyB, o); o = fma2(MB[4], ppxB, o);
            unpack2(o, b0y, b1y);
            o = fma2(MB[10], ppzB, MB[11]); o = fma2(MB[9], ppyB, o); o = fma2(MB[8], ppxB, o);
            unpack2(o, b0z, b1z);
        }

        // ---- store: 6 consecutive floats per batch, 3x STG.64 ----
        *(float2*)(mesh_out + o0)     = make_float2(a0x, a0y);
        *(float2*)(mesh_out + o0 + 2) = make_float2(a0z, b0x);
        *(float2*)(mesh_out + o0 + 4) = make_float2(b0y, b0z);
        *(float2*)(mesh_out + o1)     = make_float2(a1x, a1y);
        *(float2*)(mesh_out + o1 + 2) = make_float2(a1z, b1x);
        *(float2*)(mesh_out + o1 + 4) = make_float2(b1y, b1z);
    }
}

// ---------------------------------------------------------------------------
extern "C" void kernel_launch(void* const* d_in, const int* in_sizes, int n_in,
                              void* d_out, int out_size) {
    const float* joint_euler = (const float*)d_in[0];
    const float* vtx         = (const float*)d_in[1];
    const float* W           = (const float*)d_in[2];
    const float* local_pose  = (const float*)d_in[3];
    const float* gpi         = (const float*)d_in[4];
    const float* sc          = (const float*)d_in[5];
    const float* pc          = (const float*)d_in[6];
    const float* ic          = (const float*)d_in[7];
    const int*   parents     = (const int*)d_in[8];
    float* out = (float*)d_out;

    fk_kernel<<<B_, 128>>>(joint_euler, local_pose, sc, gpi, parents, out);
    dim3 grid((V_ + VT2 - 1) / VT2, B_ / NB);
    skin_kernel<<<grid, VT>>>(vtx, W, pc, ic, out + B_*J_*3);
}